// round 11
// baseline (speedup 1.0000x reference)
#include <cuda_runtime.h>
#include <cuda_bf16.h>
#include <cstdint>
#include <cstddef>

#define CB 8
#define CQ 32
#define CLE 128
#define CD 512
#define CP 32
#define CA 128

#define WSTRIDE 136   // word stride, W smem rows: bank = (8c+g) mod 32, conflict-free

// Scratch (device globals: allocation-free per harness rules)
__device__ float g_ws[CB * CP * CA];                    // (B,P,A)
__device__ float g_e[(size_t)CB * CQ * CP * CLE];       // (B,Q,P,LE) 4MB
__device__ float2 g_norm[CB * CP];                      // (max, 1/sum) per (b,p)
__device__ unsigned g_wh2[(CD / 2) * CA];               // hi bf16 pairs [kp][a]
__device__ unsigned g_wl2[(CD / 2) * CA];               // lo bf16 pairs [kp][a]

__device__ __forceinline__ float tanh_fast(float x) {
    float y;
    asm("tanh.approx.f32 %0, %1;" : "=f"(y) : "f"(x));
    return y;
}

// pack two floats to bf16x2: first arg -> low 16 bits, second -> high 16 bits
__device__ __forceinline__ unsigned pack_bf16x2(float lo, float hi) {
    unsigned r;
    asm("cvt.rn.bf16x2.f32 %0, %1, %2;" : "=r"(r) : "f"(hi), "f"(lo));
    return r;
}
__device__ __forceinline__ float bf16lo_f(unsigned p) { return __uint_as_float(p << 16); }
__device__ __forceinline__ float bf16hi_f(unsigned p) { return __uint_as_float(p & 0xffff0000u); }

__device__ __forceinline__ void mma_bf16(float acc[4],
    unsigned a0, unsigned a1, unsigned a2, unsigned a3,
    unsigned b0, unsigned b1)
{
    asm volatile(
        "mma.sync.aligned.m16n8k16.row.col.f32.bf16.bf16.f32 "
        "{%0,%1,%2,%3}, {%4,%5,%6,%7}, {%8,%9}, {%0,%1,%2,%3};"
        : "+f"(acc[0]), "+f"(acc[1]), "+f"(acc[2]), "+f"(acc[3])
        : "r"(a0), "r"(a1), "r"(a2), "r"(a3), "r"(b0), "r"(b1));
}

// ---------------------------------------------------------------------------
// PREP (single launch, grid 160):
//   blocks 0..127  : split U_w into bf16 hi/lo pairs [kp][a]
//   blocks 128..159: ws GEMM, 8 rows each: g_ws = s_j @ Ws_w^T + Ws_b
//     (s_j rows in smem -> warp-uniform broadcast; 4 cols/thread, float4 dots)
// ---------------------------------------------------------------------------
__global__ __launch_bounds__(256) void prep_kernel(
    const float* __restrict__ Uw, const float* __restrict__ sj,
    const float* __restrict__ Wsw, const float* __restrict__ bias)
{
    __shared__ float ss[8][512];   // 16KB

    const int tid = threadIdx.x;

    if (blockIdx.x < 128) {
        int i = blockIdx.x * 256 + tid;   // 0..32767
        int a = i >> 8, kp = i & 255;
        float w0 = Uw[a * CD + 2 * kp];
        float w1 = Uw[a * CD + 2 * kp + 1];
        unsigned ph = pack_bf16x2(w0, w1);
        float l0 = w0 - bf16lo_f(ph);
        float l1 = w1 - bf16hi_f(ph);
        g_wh2[kp * CA + a] = ph;
        g_wl2[kp * CA + a] = pack_bf16x2(l0, l1);
        return;
    }

    // ws GEMM: rows bm..bm+7 of the flattened (B*P, A) output
    const int bm = (blockIdx.x - 128) * 8;

    // Stage 8 s_j rows (8 x 512 floats)
    for (int i = tid; i < 1024; i += 256) {
        int r = i >> 7, kq = i & 127;
        ((float4*)ss[r])[kq] = *(const float4*)(sj + (size_t)(bm + r) * CD + 4 * kq);
    }
    __syncthreads();

    const int r  = tid >> 5;       // warp id -> row (warp-uniform)
    const int cq = tid & 31;       // 4 cols: 4cq..4cq+3

    const float* w0p = Wsw + (size_t)(4 * cq + 0) * CD;
    const float* w1p = Wsw + (size_t)(4 * cq + 1) * CD;
    const float* w2p = Wsw + (size_t)(4 * cq + 2) * CD;
    const float* w3p = Wsw + (size_t)(4 * cq + 3) * CD;

    float4 bv = *(const float4*)(bias + 4 * cq);
    float a0 = bv.x, a1 = bv.y, a2 = bv.z, a3 = bv.w;

    #pragma unroll 4
    for (int k0 = 0; k0 < CD; k0 += 4) {
        float4 s4 = *(const float4*)&ss[r][k0];
        float4 w0 = *(const float4*)(w0p + k0);
        float4 w1 = *(const float4*)(w1p + k0);
        float4 w2 = *(const float4*)(w2p + k0);
        float4 w3 = *(const float4*)(w3p + k0);
        a0 += s4.x * w0.x + s4.y * w0.y + s4.z * w0.z + s4.w * w0.w;
        a1 += s4.x * w1.x + s4.y * w1.y + s4.z * w1.z + s4.w * w1.w;
        a2 += s4.x * w2.x + s4.y * w2.y + s4.z * w2.z + s4.w * w2.w;
        a3 += s4.x * w3.x + s4.y * w3.y + s4.z * w3.z + s4.w * w3.w;
    }

    *(float4*)(g_ws + (size_t)(bm + r) * CA + 4 * cq) = make_float4(a0, a1, a2, a3);
}

// ---------------------------------------------------------------------------
// FUSED: uh GEMM (3-pass bf16 tensor-core) + score + mask, per (b,q) block.
// 256 threads, grid B*Q (R9 configuration — R10's 128-thread split regressed).
// ---------------------------------------------------------------------------
__global__ __launch_bounds__(256, 2) void fused_gemm_score_kernel(
    const float* __restrict__ A, const int* __restrict__ emask,
    const float* __restrict__ vw)
{
    __shared__ union SU {
        unsigned wt[2][2][16][WSTRIDE];   // [stage][hi/lo][kp_local][n] 34.8KB
        float    ws[CP * CA];             // 16KB (phase 2)
    } sm;
    __shared__ int msk[CLE];

    const int tid  = threadIdx.x;
    const int wid  = tid >> 5;
    const int lane = tid & 31;
    const int g    = lane >> 2;   // groupID
    const int c    = lane & 3;    // threadID in group

    const int bq   = blockIdx.x;
    const int row0 = bq * 128 + wid * 16;

    float acc[16][4];
    #pragma unroll
    for (int i = 0; i < 16; i++)
        #pragma unroll
        for (int j = 0; j < 4; j++) acc[i][j] = 0.f;

    const float* Arow0 = A + (size_t)(row0 + g) * CD;
    const float* Arow1 = A + (size_t)(row0 + g + 8) * CD;

    auto issueW = [&](int kt, int s) {
        const int kp0 = kt * 16;
        #pragma unroll
        for (int i = 0; i < 4; i++) {
            int idx = tid + i * 256;
            int mat = idx >> 9, rem = idx & 511;
            int r = rem >> 5, m = rem & 31;
            unsigned dst = (unsigned)__cvta_generic_to_shared(&sm.wt[s][mat][r][4 * m]);
            const unsigned* src = (mat ? g_wl2 : g_wh2) + (size_t)(kp0 + r) * CA + 4 * m;
            asm volatile("cp.async.ca.shared.global [%0], [%1], 16;\n"
                         :: "r"(dst), "l"(src));
        }
        asm volatile("cp.async.commit_group;\n");
    };

    issueW(0, 0);
    float2 arc0[4], arc1[4], arn0[4], arn1[4];
    #pragma unroll
    for (int j = 0; j < 4; j++) {
        arc0[j] = *(const float2*)(Arow0 + 8 * j + 2 * c);
        arc1[j] = *(const float2*)(Arow1 + 8 * j + 2 * c);
    }
    asm volatile("cp.async.wait_group 0;\n");
    __syncthreads();

    for (int kt = 0; kt < 16; kt++) {
        const int cur = kt & 1;

        if (kt < 15) {
            issueW(kt + 1, cur ^ 1);
            const int k0n = (kt + 1) * 32;
            #pragma unroll
            for (int j = 0; j < 4; j++) {
                arn0[j] = *(const float2*)(Arow0 + k0n + 8 * j + 2 * c);
                arn1[j] = *(const float2*)(Arow1 + k0n + 8 * j + 2 * c);
            }
        }

        #pragma unroll
        for (int ks = 0; ks < 2; ks++) {
            float2 p00 = arc0[2 * ks], p01 = arc0[2 * ks + 1];
            float2 p10 = arc1[2 * ks], p11 = arc1[2 * ks + 1];

            unsigned ah0 = pack_bf16x2(p00.x, p00.y);
            unsigned ah1 = pack_bf16x2(p10.x, p10.y);
            unsigned ah2 = pack_bf16x2(p01.x, p01.y);
            unsigned ah3 = pack_bf16x2(p11.x, p11.y);
            unsigned al0 = pack_bf16x2(p00.x - bf16lo_f(ah0), p00.y - bf16hi_f(ah0));
            unsigned al1 = pack_bf16x2(p10.x - bf16lo_f(ah1), p10.y - bf16hi_f(ah1));
            unsigned al2 = pack_bf16x2(p01.x - bf16lo_f(ah2), p01.y - bf16hi_f(ah2));
            unsigned al3 = pack_bf16x2(p11.x - bf16lo_f(ah3), p11.y - bf16hi_f(ah3));

            const unsigned* bh_r0 = &sm.wt[cur][0][ks * 8 + c][0];
            const unsigned* bh_r1 = &sm.wt[cur][0][ks * 8 + 4 + c][0];
            const unsigned* bl_r0 = &sm.wt[cur][1][ks * 8 + c][0];
            const unsigned* bl_r1 = &sm.wt[cur][1][ks * 8 + 4 + c][0];

            #pragma unroll
            for (int ni = 0; ni < 16; ni++) {
                unsigned bh0 = bh_r0[ni * 8 + g];
                unsigned bh1 = bh_r1[ni * 8 + g];
                unsigned bl0 = bl_r0[ni * 8 + g];
                unsigned bl1 = bl_r1[ni * 8 + g];
                mma_bf16(acc[ni], ah0, ah1, ah2, ah3, bh0, bh1);
                mma_bf16(acc[ni], al0, al1, al2, al3, bh0, bh1);
                mma_bf16(acc[ni], ah0, ah1, ah2, ah3, bl0, bl1);
            }
        }

        if (kt < 15) {
            asm volatile("cp.async.wait_group 0;\n");
            #pragma unroll
            for (int j = 0; j < 4; j++) { arc0[j] = arn0[j]; arc1[j] = arn1[j]; }
        }
        __syncthreads();   // also guards buffer reuse + union transition
    }

    // ---- Phase 2: score ----
    const int b = bq >> 5;
    const float* wsb = g_ws + (size_t)b * CP * CA;
    for (int i = tid; i < CP * CA / 4; i += 256)
        ((float4*)sm.ws)[i] = ((const float4*)wsb)[i];
    for (int i = tid; i < CLE; i += 256)
        msk[i] = emask[bq * CLE + i];

    float2 vr2[16];
    #pragma unroll
    for (int ni = 0; ni < 16; ni++)
        vr2[ni] = *(const float2*)(vw + ni * 8 + 2 * c);
    __syncthreads();

    float* ebq = g_e + (size_t)bq * CP * CLE;
    const int t0 = wid * 16 + g;
    const int t1 = t0 + 8;
    const bool live0 = (msk[t0] != 0);
    const bool live1 = (msk[t1] != 0);

    for (int p = 0; p < CP; p++) {
        const float* wp = sm.ws + p * CA;
        float s0 = 0.f, s1 = 0.f;
        #pragma unroll
        for (int ni = 0; ni < 16; ni++) {
            float2 w = *(const float2*)(wp + ni * 8 + 2 * c);
            s0 = fmaf(vr2[ni].x, tanh_fast(acc[ni][0] + w.x), s0);
            s0 = fmaf(vr2[ni].y, tanh_fast(acc[ni][1] + w.y), s0);
            s1 = fmaf(vr2[ni].x, tanh_fast(acc[ni][2] + w.x), s1);
            s1 = fmaf(vr2[ni].y, tanh_fast(acc[ni][3] + w.y), s1);
        }
        s0 += __shfl_down_sync(0xffffffffu, s0, 2, 4);
        s0 += __shfl_down_sync(0xffffffffu, s0, 1, 4);
        s1 += __shfl_down_sync(0xffffffffu, s1, 2, 4);
        s1 += __shfl_down_sync(0xffffffffu, s1, 1, 4);
        if (c == 0) {
            ebq[p * CLE + t0] = live0 ? s0 : -1000000000.0f;
            ebq[p * CLE + t1] = live1 ? s1 : -1000000000.0f;
        }
    }
}

// ---------------------------------------------------------------------------
// Reduce: per (b,p), max + sum-of-exp over joint (q,t) axis -> g_norm.
// ---------------------------------------------------------------------------
__global__ __launch_bounds__(256) void reduce_kernel()
{
    const int b = blockIdx.x >> 5;   // P=32
    const int p = blockIdx.x & 31;
    const int tid = threadIdx.x;

    __shared__ float red[8];

    float vals[16];
    float mx = -3.4e38f;
    #pragma unroll
    for (int i = 0; i < 16; i++) {
        int idx = tid + i * 256;
        int q = idx >> 7, t = idx & 127;
        float v = g_e[(((size_t)(b * CQ + q) * CP + p) << 7) + t];
        vals[i] = v;
        mx = fmaxf(mx, v);
    }
    #pragma unroll
    for (int o = 16; o > 0; o >>= 1)
        mx = fmaxf(mx, __shfl_xor_sync(0xffffffffu, mx, o));
    if ((tid & 31) == 0) red[tid >> 5] = mx;
    __syncthreads();
    float m2 = red[0];
    #pragma unroll
    for (int w = 1; w < 8; w++) m2 = fmaxf(m2, red[w]);
    __syncthreads();

    float sum = 0.f;
    #pragma unroll
    for (int i = 0; i < 16; i++)
        sum += __expf(vals[i] - m2);
    #pragma unroll
    for (int o = 16; o > 0; o >>= 1)
        sum += __shfl_xor_sync(0xffffffffu, sum, o);
    if ((tid & 31) == 0) red[tid >> 5] = sum;
    __syncthreads();
    if (tid == 0) {
        float s2 = 0.f;
        #pragma unroll
        for (int w = 0; w < 8; w++) s2 += red[w];
        g_norm[blockIdx.x] = make_float2(m2, 1.0f / s2);
    }
}

// ---------------------------------------------------------------------------
// OUT (tensor-core, softmax folded): per (b,q) block,
// out[p][d] = sum_t [exp(e[p][t]-m_p)*inv_p*rmask_p] * tok[t][d]
// bf16 3-pass split, M=32(p), K=128(t), N in 4 chunks of 128 d.
// tok tile for the next (dc,tt) is prefetched into registers across the mma.
// ---------------------------------------------------------------------------
__global__ __launch_bounds__(256) void out_bf16_kernel(
    const float* __restrict__ tok, const int* __restrict__ rmask,
    float* __restrict__ out)
{
    __shared__ unsigned a_h[64][40],  a_l[64][40];      // [tp][p] 20.5KB
    __shared__ unsigned tok_h[16][136], tok_l[16][136]; // [tp][d_chunk] 17.4KB

    const int tid  = threadIdx.x;
    const int wid  = tid >> 5;
    const int lane = tid & 31;
    const int g    = lane >> 2;
    const int c    = lane & 3;

    const int bq = blockIdx.x;
    const int b  = bq >> 5;

    // Phase A: a = exp(e - m)*inv*rmask, bf16 hi/lo pair-packed along t.
    const float* ebq = g_e + (size_t)bq * CP * CLE;
    #pragma unroll
    for (int i = 0; i < 8; i++) {
        int idx = tid + i * 256;          // 2048 items = 32p x 64tp
        int p = idx >> 6, tp = idx & 63;
        float2 nv = g_norm[b * CP + p];
        float iv = nv.y * (float)rmask[b * CP + p];
        float2 e2 = *(const float2*)(ebq + p * CLE + 2 * tp);
        float v0 = __expf(e2.x - nv.x) * iv;
        float v1 = __expf(e2.y - nv.x) * iv;
        unsigned h = pack_bf16x2(v0, v1);
        a_h[tp][p] = h;
        a_l[tp][p] = pack_bf16x2(v0 - bf16lo_f(h), v1 - bf16hi_f(h));
    }

    const float* tokbq = tok + (size_t)bq * CLE * CD;
    float* obq = out + (size_t)bq * CP * CD;
    const int nw = wid * 16;   // this warp's 16 d-cols within the 128-wide chunk

    // raw tok registers for the prefetched tile (2 items/thread)
    float4 rx0[2], rx1[2];

    auto loadRaw = [&](int dcc, int ttt) {
        #pragma unroll
        for (int i = 0; i < 2; i++) {
            int idx = tid + i * 256;      // 512 items = 16tp x 32 d-quads
            int tp = idx >> 5, dq = idx & 31;
            const float* r = tokbq + (size_t)(ttt * 32 + 2 * tp) * CD + dcc * 128 + 4 * dq;
            rx0[i] = *(const float4*)r;
            rx1[i] = *(const float4*)(r + CD);
        }
    };

    loadRaw(0, 0);

    for (int dc = 0; dc < 4; dc++) {
        const int d0 = dc * 128;

        float acc[2][2][4];
        #pragma unroll
        for (int mt = 0; mt < 2; mt++)
            #pragma unroll
            for (int ni = 0; ni < 2; ni++)
                #pragma unroll
                for (int j = 0; j < 4; j++) acc[mt][ni][j] = 0.f;

        for (int tt = 0; tt < 4; tt++) {
            __syncthreads();
            // Convert prefetched raw tile -> hi/lo pair-packed smem.
            #pragma unroll
            for (int i = 0; i < 2; i++) {
                int idx = tid + i * 256;
                int tp = idx >> 5, dq = idx & 31;
                float4 x0 = rx0[i], x1 = rx1[i];
                unsigned h0 = pack_bf16x2(x0.x, x1.x);
                unsigned h1 = pack_bf16x2(x0.y, x1.y);
                unsigned h2 = pack_bf16x2(x0.z, x1.z);
                unsigned h3 = pack_bf16x2(x0.w, x1.w);
                *(uint4*)&tok_h[tp][4 * dq] = make_uint4(h0, h1, h2, h3);
                unsigned l0 = pack_bf16x2(x0.x - bf16lo_f(h0), x1.x - bf16hi_f(h0));
                unsigned l1 = pack_bf16x2(x0.y - bf16lo_f(h1), x1.y - bf16hi_f(h1));
                unsigned l2 = pack_bf16x2(x0.z - bf16lo_f(h2), x1.z - bf16hi_f(h2));
                unsigned l3 = pack_bf16x2(x0.w - bf16lo_f(h3), x1.w - bf16hi_f(h3));
                *(uint4*)&tok_l[tp][4 * dq] = make_uint4(l0, l1, l2, l3);
            }
            // Prefetch the next tile's raw data (overlaps the mma section).
            {
                int ntt = tt + 1, ndc = dc;
                if (ntt == 4) { ntt = 0; ndc = dc + 1; }
                if (ndc < 4) loadRaw(ndc, ntt);
            }
            __syncthreads();

            #pragma unroll
            for (int kc = 0; kc < 2; kc++) {
                const int tb = tt * 16 + kc * 8;   // global tp base of this k16
                unsigned Ah[2][4], Al[2][4];
                #pragma unroll
                for (int mt = 0; mt < 2; mt++) {
                    const int m0 = mt * 16;
                    Ah[mt][0] = a_h[tb + c][m0 + g];
                    Ah[mt][1] = a_h[tb + c][m0 + g + 8];
                    Ah[mt][2] = a_h[tb + 4 + c][m0 + g];
                    Ah[mt][3] = a_h[tb + 4 + c][m0 + g + 8];
                    Al[mt][0] = a_l[tb + c][m0 + g];
                    Al[mt][1] = a_l[tb + c][m0 + g + 8];
                    Al[mt][2] = a_l[tb + 4 + c][m0 + g];
                    Al[mt][3] = a_l[tb + 4 + c][m0 + g + 8];
                }
                #pragma unroll
                for (int ni = 0; ni < 2; ni++) {
                    const int n = nw + ni * 8 + g;
                    unsigned bh0 = tok_h[kc * 8 + c][n];
                    unsigned bh1 = tok_h[kc * 8 + 4 + c][n];
                    unsigned bl0 = tok_l[kc * 8 + c][n];
                    unsigned bl1 = tok_l[kc * 8 + 4 + c][n];
                    #pragma unroll
                    for (int mt = 0; mt < 2; mt++) {
                        mma_bf16(acc[mt][ni], Ah[mt][0], Ah[mt][1], Ah[mt][2], Ah[mt][3], bh0, bh1);
                        mma_bf16(acc[mt][ni], Al[mt][0], Al[mt][1], Al[mt][2], Al[mt][3], bh0, bh1);
                        mma_bf16(acc[mt][ni], Ah[mt][0], Ah[mt][1], Ah[mt][2], Ah[mt][3], bl0, bl1);
                    }
                }
            }
        }

        // Epilogue for this d-chunk.
        #pragma unroll
        for (int mt = 0; mt < 2; mt++) {
            const int p0 = mt * 16 + g;
            #pragma unroll
            for (int ni = 0; ni < 2; ni++) {
                const int d = d0 + nw + ni * 8 + 2 * c;
                *(float2*)(obq + (size_t)p0 * CD + d) =
                    make_float2(acc[mt][ni][0], acc[mt][ni][1]);
                *(float2*)(obq + (size_t)(p0 + 8) * CD + d) =
                    make_float2(acc[mt][ni][2], acc[mt][ni][3]);
            }
        }
    }
}

// ---------------------------------------------------------------------------
extern "C" void kernel_launch(void* const* d_in, const int* in_sizes, int n_in,
                              void* d_out, int out_size)
{
    const float* tok   = (const float*)d_in[0];   // exp_tokens (B,Q,LE,D)
    const int*   emask = (const int*)  d_in[1];   // exp_mask   (B,Q,LE)
    const float* sj    = (const float*)d_in[2];   // s_j        (B,P,D)
    const int*   rmask = (const int*)  d_in[3];   // req_mask   (B,P)
    const float* Wsw   = (const float*)d_in[4];   // Ws_w       (A,D)
    const float* Wsb   = (const float*)d_in[5];   // Ws_b       (A,)
    const float* Uw    = (const float*)d_in[6];   // U_w        (A,D)
    const float* vw    = (const float*)d_in[7];   // v_w        (1,A)
    float* out = (float*)d_out;                   // (B,Q,P,D)

    prep_kernel<<<160, 256>>>(Uw, sj, Wsw, Wsb);                   // idx 0
    fused_gemm_score_kernel<<<CB * CQ, 256>>>(tok, emask, vw);     // idx 1
    reduce_kernel<<<CB * CP, 256>>>();                             // idx 2
    out_bf16_kernel<<<CB * CQ, 256>>>(tok, rmask, out);            // idx 3 (profiled)
}

// round 14
// speedup vs baseline: 1.4047x; 1.4047x over previous
#include <cuda_runtime.h>
#include <cuda_bf16.h>
#include <cstdint>
#include <cstddef>

#define CB 8
#define CQ 32
#define CLE 128
#define CD 512
#define CP 32
#define CA 128

#define WSTRIDE 136   // word stride, W smem rows: bank = (8c+g) mod 32, conflict-free

// Scratch (device globals: allocation-free per harness rules)
__device__ float g_ws[CB * CP * CA];                    // (B,P,A)
__device__ float g_e[(size_t)CB * CQ * CP * CLE];       // (B,Q,P,LE) 4MB
__device__ float2 g_norm[CB * CP];                      // (max, 1/sum) per (b,p)
__device__ unsigned g_wh2[(CD / 2) * CA];               // hi bf16 pairs [kp][a]
__device__ unsigned g_wl2[(CD / 2) * CA];               // lo bf16 pairs [kp][a]

__device__ __forceinline__ float tanh_fast(float x) {
    float y;
    asm("tanh.approx.f32 %0, %1;" : "=f"(y) : "f"(x));
    return y;
}

// pack two floats to bf16x2: first arg -> low 16 bits, second -> high 16 bits
__device__ __forceinline__ unsigned pack_bf16x2(float lo, float hi) {
    unsigned r;
    asm("cvt.rn.bf16x2.f32 %0, %1, %2;" : "=r"(r) : "f"(hi), "f"(lo));
    return r;
}
__device__ __forceinline__ float bf16lo_f(unsigned p) { return __uint_as_float(p << 16); }
__device__ __forceinline__ float bf16hi_f(unsigned p) { return __uint_as_float(p & 0xffff0000u); }

__device__ __forceinline__ void mma_bf16(float acc[4],
    unsigned a0, unsigned a1, unsigned a2, unsigned a3,
    unsigned b0, unsigned b1)
{
    asm volatile(
        "mma.sync.aligned.m16n8k16.row.col.f32.bf16.bf16.f32 "
        "{%0,%1,%2,%3}, {%4,%5,%6,%7}, {%8,%9}, {%0,%1,%2,%3};"
        : "+f"(acc[0]), "+f"(acc[1]), "+f"(acc[2]), "+f"(acc[3])
        : "r"(a0), "r"(a1), "r"(a2), "r"(a3), "r"(b0), "r"(b1));
}

// ---------------------------------------------------------------------------
// PREP (single launch, grid 160):
//   blocks 0..127  : split U_w into bf16 hi/lo pairs [kp][a]
//   blocks 128..159: ws GEMM, 8 rows/block: g_ws = s_j @ Ws_w^T + Ws_b.
//     s_j rows staged in smem (broadcast reads); Ws_w staged per 32-k tile
//     TRANSPOSED to wt[k][a] (stride 132) -> coalesced gmem, conflict-free LDS.
// ---------------------------------------------------------------------------
__global__ __launch_bounds__(256) void prep_kernel(
    const float* __restrict__ Uw, const float* __restrict__ sj,
    const float* __restrict__ Wsw, const float* __restrict__ bias)
{
    __shared__ float ss[8][512];     // 16KB
    __shared__ float wt[32][132];    // 16.5KB, transposed W tile

    const int tid = threadIdx.x;

    if (blockIdx.x < 128) {
        int i = blockIdx.x * 256 + tid;   // 0..32767
        int a = i >> 8, kp = i & 255;
        float w0 = Uw[a * CD + 2 * kp];
        float w1 = Uw[a * CD + 2 * kp + 1];
        unsigned ph = pack_bf16x2(w0, w1);
        float l0 = w0 - bf16lo_f(ph);
        float l1 = w1 - bf16hi_f(ph);
        g_wh2[kp * CA + a] = ph;
        g_wl2[kp * CA + a] = pack_bf16x2(l0, l1);
        return;
    }

    // ws GEMM: rows bm..bm+7 of the flattened (B*P, A) output
    const int bm = (blockIdx.x - 128) * 8;

    // Stage 8 s_j rows (8 x 512 floats), coalesced float4
    for (int i = tid; i < 1024; i += 256) {
        int r = i >> 7, kq = i & 127;
        ((float4*)ss[r])[kq] = *(const float4*)(sj + (size_t)(bm + r) * CD + 4 * kq);
    }

    const int r  = tid >> 5;       // warp id -> output row (warp-uniform)
    const int cq = tid & 31;       // 4 cols: 4cq..4cq+3

    float4 bv = *(const float4*)(bias + 4 * cq);
    float a0 = bv.x, a1 = bv.y, a2 = bv.z, a3 = bv.w;

    for (int kt = 0; kt < 16; kt++) {
        const int k0 = kt * 32;
        __syncthreads();
        // Load W tile [128 a x 32 k] = 1024 float4s, transpose into wt[k][a].
        #pragma unroll
        for (int i = 0; i < 4; i++) {
            int idx = tid + i * 256;          // 1024 items = 128a x 8 kquads
            int a = idx >> 3, kq = idx & 7;
            float4 w4 = *(const float4*)(Wsw + (size_t)a * CD + k0 + 4 * kq);
            wt[4 * kq + 0][a] = w4.x;
            wt[4 * kq + 1][a] = w4.y;
            wt[4 * kq + 2][a] = w4.z;
            wt[4 * kq + 3][a] = w4.w;
        }
        __syncthreads();

        #pragma unroll
        for (int k = 0; k < 32; k++) {
            float s = ss[r][k0 + k];                        // broadcast
            float4 w = *(const float4*)&wt[k][4 * cq];      // conflict-free
            a0 = fmaf(s, w.x, a0);
            a1 = fmaf(s, w.y, a1);
            a2 = fmaf(s, w.z, a2);
            a3 = fmaf(s, w.w, a3);
        }
    }

    *(float4*)(g_ws + (size_t)(bm + r) * CA + 4 * cq) = make_float4(a0, a1, a2, a3);
}

// ---------------------------------------------------------------------------
// FUSED: uh GEMM (3-pass bf16 tensor-core) + score + mask, per (b,q) block.
// 256 threads, grid B*Q.
// ---------------------------------------------------------------------------
__global__ __launch_bounds__(256, 2) void fused_gemm_score_kernel(
    const float* __restrict__ A, const int* __restrict__ emask,
    const float* __restrict__ vw)
{
    __shared__ union SU {
        unsigned wt[2][2][16][WSTRIDE];   // [stage][hi/lo][kp_local][n] 34.8KB
        float    ws[CP * CA];             // 16KB (phase 2)
    } sm;
    __shared__ int msk[CLE];

    const int tid  = threadIdx.x;
    const int wid  = tid >> 5;
    const int lane = tid & 31;
    const int g    = lane >> 2;   // groupID
    const int c    = lane & 3;    // threadID in group

    const int bq   = blockIdx.x;
    const int row0 = bq * 128 + wid * 16;

    float acc[16][4];
    #pragma unroll
    for (int i = 0; i < 16; i++)
        #pragma unroll
        for (int j = 0; j < 4; j++) acc[i][j] = 0.f;

    const float* Arow0 = A + (size_t)(row0 + g) * CD;
    const float* Arow1 = A + (size_t)(row0 + g + 8) * CD;

    auto issueW = [&](int kt, int s) {
        const int kp0 = kt * 16;
        #pragma unroll
        for (int i = 0; i < 4; i++) {
            int idx = tid + i * 256;
            int mat = idx >> 9, rem = idx & 511;
            int r = rem >> 5, m = rem & 31;
            unsigned dst = (unsigned)__cvta_generic_to_shared(&sm.wt[s][mat][r][4 * m]);
            const unsigned* src = (mat ? g_wl2 : g_wh2) + (size_t)(kp0 + r) * CA + 4 * m;
            asm volatile("cp.async.ca.shared.global [%0], [%1], 16;\n"
                         :: "r"(dst), "l"(src));
        }
        asm volatile("cp.async.commit_group;\n");
    };

    issueW(0, 0);
    float2 arc0[4], arc1[4], arn0[4], arn1[4];
    #pragma unroll
    for (int j = 0; j < 4; j++) {
        arc0[j] = *(const float2*)(Arow0 + 8 * j + 2 * c);
        arc1[j] = *(const float2*)(Arow1 + 8 * j + 2 * c);
    }
    asm volatile("cp.async.wait_group 0;\n");
    __syncthreads();

    for (int kt = 0; kt < 16; kt++) {
        const int cur = kt & 1;

        if (kt < 15) {
            issueW(kt + 1, cur ^ 1);
            const int k0n = (kt + 1) * 32;
            #pragma unroll
            for (int j = 0; j < 4; j++) {
                arn0[j] = *(const float2*)(Arow0 + k0n + 8 * j + 2 * c);
                arn1[j] = *(const float2*)(Arow1 + k0n + 8 * j + 2 * c);
            }
        }

        #pragma unroll
        for (int ks = 0; ks < 2; ks++) {
            float2 p00 = arc0[2 * ks], p01 = arc0[2 * ks + 1];
            float2 p10 = arc1[2 * ks], p11 = arc1[2 * ks + 1];

            unsigned ah0 = pack_bf16x2(p00.x, p00.y);
            unsigned ah1 = pack_bf16x2(p10.x, p10.y);
            unsigned ah2 = pack_bf16x2(p01.x, p01.y);
            unsigned ah3 = pack_bf16x2(p11.x, p11.y);
            unsigned al0 = pack_bf16x2(p00.x - bf16lo_f(ah0), p00.y - bf16hi_f(ah0));
            unsigned al1 = pack_bf16x2(p10.x - bf16lo_f(ah1), p10.y - bf16hi_f(ah1));
            unsigned al2 = pack_bf16x2(p01.x - bf16lo_f(ah2), p01.y - bf16hi_f(ah2));
            unsigned al3 = pack_bf16x2(p11.x - bf16lo_f(ah3), p11.y - bf16hi_f(ah3));

            const unsigned* bh_r0 = &sm.wt[cur][0][ks * 8 + c][0];
            const unsigned* bh_r1 = &sm.wt[cur][0][ks * 8 + 4 + c][0];
            const unsigned* bl_r0 = &sm.wt[cur][1][ks * 8 + c][0];
            const unsigned* bl_r1 = &sm.wt[cur][1][ks * 8 + 4 + c][0];

            #pragma unroll
            for (int ni = 0; ni < 16; ni++) {
                unsigned bh0 = bh_r0[ni * 8 + g];
                unsigned bh1 = bh_r1[ni * 8 + g];
                unsigned bl0 = bl_r0[ni * 8 + g];
                unsigned bl1 = bl_r1[ni * 8 + g];
                mma_bf16(acc[ni], ah0, ah1, ah2, ah3, bh0, bh1);
                mma_bf16(acc[ni], al0, al1, al2, al3, bh0, bh1);
                mma_bf16(acc[ni], ah0, ah1, ah2, ah3, bl0, bl1);
            }
        }

        if (kt < 15) {
            asm volatile("cp.async.wait_group 0;\n");
            #pragma unroll
            for (int j = 0; j < 4; j++) { arc0[j] = arn0[j]; arc1[j] = arn1[j]; }
        }
        __syncthreads();   // also guards buffer reuse + union transition
    }

    // ---- Phase 2: score ----
    const int b = bq >> 5;
    const float* wsb = g_ws + (size_t)b * CP * CA;
    for (int i = tid; i < CP * CA / 4; i += 256)
        ((float4*)sm.ws)[i] = ((const float4*)wsb)[i];
    for (int i = tid; i < CLE; i += 256)
        msk[i] = emask[bq * CLE + i];

    float2 vr2[16];
    #pragma unroll
    for (int ni = 0; ni < 16; ni++)
        vr2[ni] = *(const float2*)(vw + ni * 8 + 2 * c);
    __syncthreads();

    float* ebq = g_e + (size_t)bq * CP * CLE;
    const int t0 = wid * 16 + g;
    const int t1 = t0 + 8;
    const bool live0 = (msk[t0] != 0);
    const bool live1 = (msk[t1] != 0);

    for (int p = 0; p < CP; p++) {
        const float* wp = sm.ws + p * CA;
        float s0 = 0.f, s1 = 0.f;
        #pragma unroll
        for (int ni = 0; ni < 16; ni++) {
            float2 w = *(const float2*)(wp + ni * 8 + 2 * c);
            s0 = fmaf(vr2[ni].x, tanh_fast(acc[ni][0] + w.x), s0);
            s0 = fmaf(vr2[ni].y, tanh_fast(acc[ni][1] + w.y), s0);
            s1 = fmaf(vr2[ni].x, tanh_fast(acc[ni][2] + w.x), s1);
            s1 = fmaf(vr2[ni].y, tanh_fast(acc[ni][3] + w.y), s1);
        }
        s0 += __shfl_down_sync(0xffffffffu, s0, 2, 4);
        s0 += __shfl_down_sync(0xffffffffu, s0, 1, 4);
        s1 += __shfl_down_sync(0xffffffffu, s1, 2, 4);
        s1 += __shfl_down_sync(0xffffffffu, s1, 1, 4);
        if (c == 0) {
            ebq[p * CLE + t0] = live0 ? s0 : -1000000000.0f;
            ebq[p * CLE + t1] = live1 ? s1 : -1000000000.0f;
        }
    }
}

// ---------------------------------------------------------------------------
// Reduce: per (b,p), max + sum-of-exp over joint (q,t) axis -> g_norm.
// ---------------------------------------------------------------------------
__global__ __launch_bounds__(256) void reduce_kernel()
{
    const int b = blockIdx.x >> 5;   // P=32
    const int p = blockIdx.x & 31;
    const int tid = threadIdx.x;

    __shared__ float red[8];

    float vals[16];
    float mx = -3.4e38f;
    #pragma unroll
    for (int i = 0; i < 16; i++) {
        int idx = tid + i * 256;
        int q = idx >> 7, t = idx & 127;
        float v = g_e[(((size_t)(b * CQ + q) * CP + p) << 7) + t];
        vals[i] = v;
        mx = fmaxf(mx, v);
    }
    #pragma unroll
    for (int o = 16; o > 0; o >>= 1)
        mx = fmaxf(mx, __shfl_xor_sync(0xffffffffu, mx, o));
    if ((tid & 31) == 0) red[tid >> 5] = mx;
    __syncthreads();
    float m2 = red[0];
    #pragma unroll
    for (int w = 1; w < 8; w++) m2 = fmaxf(m2, red[w]);
    __syncthreads();

    float sum = 0.f;
    #pragma unroll
    for (int i = 0; i < 16; i++)
        sum += __expf(vals[i] - m2);
    #pragma unroll
    for (int o = 16; o > 0; o >>= 1)
        sum += __shfl_xor_sync(0xffffffffu, sum, o);
    if ((tid & 31) == 0) red[tid >> 5] = sum;
    __syncthreads();
    if (tid == 0) {
        float s2 = 0.f;
        #pragma unroll
        for (int w = 0; w < 8; w++) s2 += red[w];
        g_norm[blockIdx.x] = make_float2(m2, 1.0f / s2);
    }
}

// ---------------------------------------------------------------------------
// OUT (tensor-core, softmax folded): per (b,q) block,
// out[p][d] = sum_t [exp(e[p][t]-m_p)*inv_p*rmask_p] * tok[t][d]
// bf16 3-pass split, M=32(p), K=128(t), N in 4 chunks of 128 d.
// tok tile for the next (dc,tt) is prefetched into registers across the mma.
// ---------------------------------------------------------------------------
__global__ __launch_bounds__(256) void out_bf16_kernel(
    const float* __restrict__ tok, const int* __restrict__ rmask,
    float* __restrict__ out)
{
    __shared__ unsigned a_h[64][40],  a_l[64][40];      // [tp][p] 20.5KB
    __shared__ unsigned tok_h[16][136], tok_l[16][136]; // [tp][d_chunk] 17.4KB

    const int tid  = threadIdx.x;
    const int wid  = tid >> 5;
    const int lane = tid & 31;
    const int g    = lane >> 2;
    const int c    = lane & 3;

    const int bq = blockIdx.x;
    const int b  = bq >> 5;

    // Phase A: a = exp(e - m)*inv*rmask, bf16 hi/lo pair-packed along t.
    const float* ebq = g_e + (size_t)bq * CP * CLE;
    #pragma unroll
    for (int i = 0; i < 8; i++) {
        int idx = tid + i * 256;          // 2048 items = 32p x 64tp
        int p = idx >> 6, tp = idx & 63;
        float2 nv = g_norm[b * CP + p];
        float iv = nv.y * (float)rmask[b * CP + p];
        float2 e2 = *(const float2*)(ebq + p * CLE + 2 * tp);
        float v0 = __expf(e2.x - nv.x) * iv;
        float v1 = __expf(e2.y - nv.x) * iv;
        unsigned h = pack_bf16x2(v0, v1);
        a_h[tp][p] = h;
        a_l[tp][p] = pack_bf16x2(v0 - bf16lo_f(h), v1 - bf16hi_f(h));
    }

    const float* tokbq = tok + (size_t)bq * CLE * CD;
    float* obq = out + (size_t)bq * CP * CD;
    const int nw = wid * 16;   // this warp's 16 d-cols within the 128-wide chunk

    // raw tok registers for the prefetched tile (2 items/thread)
    float4 rx0[2], rx1[2];

    auto loadRaw = [&](int dcc, int ttt) {
        #pragma unroll
        for (int i = 0; i < 2; i++) {
            int idx = tid + i * 256;      // 512 items = 16tp x 32 d-quads
            int tp = idx >> 5, dq = idx & 31;
            const float* r = tokbq + (size_t)(ttt * 32 + 2 * tp) * CD + dcc * 128 + 4 * dq;
            rx0[i] = *(const float4*)r;
            rx1[i] = *(const float4*)(r + CD);
        }
    };

    loadRaw(0, 0);

    for (int dc = 0; dc < 4; dc++) {
        const int d0 = dc * 128;

        float acc[2][2][4];
        #pragma unroll
        for (int mt = 0; mt < 2; mt++)
            #pragma unroll
            for (int ni = 0; ni < 2; ni++)
                #pragma unroll
                for (int j = 0; j < 4; j++) acc[mt][ni][j] = 0.f;

        for (int tt = 0; tt < 4; tt++) {
            __syncthreads();
            // Convert prefetched raw tile -> hi/lo pair-packed smem.
            #pragma unroll
            for (int i = 0; i < 2; i++) {
                int idx = tid + i * 256;
                int tp = idx >> 5, dq = idx & 31;
                float4 x0 = rx0[i], x1 = rx1[i];
                unsigned h0 = pack_bf16x2(x0.x, x1.x);
                unsigned h1 = pack_bf16x2(x0.y, x1.y);
                unsigned h2 = pack_bf16x2(x0.z, x1.z);
                unsigned h3 = pack_bf16x2(x0.w, x1.w);
                *(uint4*)&tok_h[tp][4 * dq] = make_uint4(h0, h1, h2, h3);
                unsigned l0 = pack_bf16x2(x0.x - bf16lo_f(h0), x1.x - bf16hi_f(h0));
                unsigned l1 = pack_bf16x2(x0.y - bf16lo_f(h1), x1.y - bf16hi_f(h1));
                unsigned l2 = pack_bf16x2(x0.z - bf16lo_f(h2), x1.z - bf16hi_f(h2));
                unsigned l3 = pack_bf16x2(x0.w - bf16lo_f(h3), x1.w - bf16hi_f(h3));
                *(uint4*)&tok_l[tp][4 * dq] = make_uint4(l0, l1, l2, l3);
            }
            // Prefetch the next tile's raw data (overlaps the mma section).
            {
                int ntt = tt + 1, ndc = dc;
                if (ntt == 4) { ntt = 0; ndc = dc + 1; }
                if (ndc < 4) loadRaw(ndc, ntt);
            }
            __syncthreads();

            #pragma unroll
            for (int kc = 0; kc < 2; kc++) {
                const int tb = tt * 16 + kc * 8;   // global tp base of this k16
                unsigned Ah[2][4], Al[2][4];
                #pragma unroll
                for (int mt = 0; mt < 2; mt++) {
                    const int m0 = mt * 16;
                    Ah[mt][0] = a_h[tb + c][m0 + g];
                    Ah[mt][1] = a_h[tb + c][m0 + g + 8];
                    Ah[mt][2] = a_h[tb + 4 + c][m0 + g];
                    Ah[mt][3] = a_h[tb + 4 + c][m0 + g + 8];
                    Al[mt][0] = a_l[tb + c][m0 + g];
                    Al[mt][1] = a_l[tb + c][m0 + g + 8];
                    Al[mt][2] = a_l[tb + 4 + c][m0 + g];
                    Al[mt][3] = a_l[tb + 4 + c][m0 + g + 8];
                }
                #pragma unroll
                for (int ni = 0; ni < 2; ni++) {
                    const int n = nw + ni * 8 + g;
                    unsigned bh0 = tok_h[kc * 8 + c][n];
                    unsigned bh1 = tok_h[kc * 8 + 4 + c][n];
                    unsigned bl0 = tok_l[kc * 8 + c][n];
                    unsigned bl1 = tok_l[kc * 8 + 4 + c][n];
                    #pragma unroll
                    for (int mt = 0; mt < 2; mt++) {
                        mma_bf16(acc[mt][ni], Ah[mt][0], Ah[mt][1], Ah[mt][2], Ah[mt][3], bh0, bh1);
                        mma_bf16(acc[mt][ni], Al[mt][0], Al[mt][1], Al[mt][2], Al[mt][3], bh0, bh1);
                        mma_bf16(acc[mt][ni], Ah[mt][0], Ah[mt][1], Ah[mt][2], Ah[mt][3], bl0, bl1);
                    }
                }
            }
        }

        // Epilogue for this d-chunk.
        #pragma unroll
        for (int mt = 0; mt < 2; mt++) {
            const int p0 = mt * 16 + g;
            #pragma unroll
            for (int ni = 0; ni < 2; ni++) {
                const int d = d0 + nw + ni * 8 + 2 * c;
                *(float2*)(obq + (size_t)p0 * CD + d) =
                    make_float2(acc[mt][ni][0], acc[mt][ni][1]);
                *(float2*)(obq + (size_t)(p0 + 8) * CD + d) =
                    make_float2(acc[mt][ni][2], acc[mt][ni][3]);
            }
        }
    }
}

// ---------------------------------------------------------------------------
extern "C" void kernel_launch(void* const* d_in, const int* in_sizes, int n_in,
                              void* d_out, int out_size)
{
    const float* tok   = (const float*)d_in[0];   // exp_tokens (B,Q,LE,D)
    const int*   emask = (const int*)  d_in[1];   // exp_mask   (B,Q,LE)
    const float* sj    = (const float*)d_in[2];   // s_j        (B,P,D)
    const int*   rmask = (const int*)  d_in[3];   // req_mask   (B,P)
    const float* Wsw   = (const float*)d_in[4];   // Ws_w       (A,D)
    const float* Wsb   = (const float*)d_in[5];   // Ws_b       (A,)
    const float* Uw    = (const float*)d_in[6];   // U_w        (A,D)
    const float* vw    = (const float*)d_in[7];   // v_w        (1,A)
    float* out = (float*)d_out;                   // (B,Q,P,D)

    prep_kernel<<<160, 256>>>(Uw, sj, Wsw, Wsb);                   // idx 0
    fused_gemm_score_kernel<<<CB * CQ, 256>>>(tok, emask, vw);     // idx 1
    reduce_kernel<<<CB * CP, 256>>>();                             // idx 2
    out_bf16_kernel<<<CB * CQ, 256>>>(tok, rmask, out);            // idx 3 (profiled)
}